// round 2
// baseline (speedup 1.0000x reference)
#include <cuda_runtime.h>
#include <math.h>

#define NN 50000
#define EE 800000
#define INC 128
#define HCD 128
#define HEADS 4
#define OUTC 64
#define ED 32
#define NEG 0.2f

// ---------------- scratch (device globals) ------------------------------------
__device__ float g_xl1[NN * HCD];
__device__ float g_xr1[NN * HCD];
__device__ float g_h  [NN * HCD];
__device__ float g_xl2[NN * OUTC];
__device__ float g_xr2[NN * OUTC];
__device__ float g_a1p[EE * HEADS];   // logits layer1, CSR-permuted, [pos][head]
__device__ float g_a2p[EE];           // logits layer2, CSR-permuted
__device__ int   g_deg[NN];
__device__ int   g_rowptr[NN + 1];
__device__ int   g_cursor[NN];
__device__ int   g_epos[EE];          // edge -> CSR slot
__device__ int   g_srcp[EE];          // CSR slot -> src node

// ---------------- f32x2 helpers ------------------------------------------------
__device__ __forceinline__ unsigned long long pack2(float x, float y) {
    unsigned long long r;
    asm("mov.b64 %0, {%1, %2};" : "=l"(r) : "f"(x), "f"(y));
    return r;
}
__device__ __forceinline__ void unpack2(unsigned long long v, float& lo, float& hi) {
    asm("mov.b64 {%0, %1}, %2;" : "=f"(lo), "=f"(hi) : "l"(v));
}
__device__ __forceinline__ void fma2(unsigned long long& acc, unsigned long long a,
                                     unsigned long long b) {
    asm("fma.rn.f32x2 %0, %1, %2, %0;" : "+l"(acc) : "l"(a), "l"(b));
}
__device__ __forceinline__ float lrelu(float x) { return x > 0.f ? x : NEG * x; }

// ---------------- CSR build ---------------------------------------------------
__global__ void csr_count_kernel(const int* __restrict__ dst) {
    int e = blockIdx.x * blockDim.x + threadIdx.x;
    if (e < EE) atomicAdd(&g_deg[dst[e]], 1);
}

__global__ void scan_kernel() {
    __shared__ int wtot[32];
    __shared__ int carry_sm;
    int t = threadIdx.x, lane = t & 31, wid = t >> 5;
    if (t == 0) carry_sm = 0;
    __syncthreads();
    for (int base = 0; base < NN; base += 4096) {
        int carry = carry_sm;
        int idx = base + t * 4;
        int4 v = make_int4(0, 0, 0, 0);
        if (idx + 3 < NN) v = *(const int4*)&g_deg[idx];
        else {
            if (idx     < NN) v.x = g_deg[idx];
            if (idx + 1 < NN) v.y = g_deg[idx + 1];
            if (idx + 2 < NN) v.z = g_deg[idx + 2];
        }
        int s1 = v.x + v.y, s2 = s1 + v.z, tsum = s2 + v.w;
        int sc = tsum;
        #pragma unroll
        for (int off = 1; off < 32; off <<= 1) {
            int u = __shfl_up_sync(0xffffffffu, sc, off);
            if (lane >= off) sc += u;
        }
        if (lane == 31) wtot[wid] = sc;
        __syncthreads();
        if (wid == 0) {
            int wv = wtot[lane];
            int ws = wv;
            #pragma unroll
            for (int off = 1; off < 32; off <<= 1) {
                int u = __shfl_up_sync(0xffffffffu, ws, off);
                if (lane >= off) ws += u;
            }
            wtot[lane] = ws - wv;   // exclusive warp prefix
        }
        __syncthreads();
        int off0 = carry + wtot[wid] + (sc - tsum);
        if (idx     < NN) { g_rowptr[idx]     = off0;       g_cursor[idx]     = off0; }
        if (idx + 1 < NN) { int o = off0 + v.x; g_rowptr[idx + 1] = o; g_cursor[idx + 1] = o; }
        if (idx + 2 < NN) { int o = off0 + s1;  g_rowptr[idx + 2] = o; g_cursor[idx + 2] = o; }
        if (idx + 3 < NN) { int o = off0 + s2;  g_rowptr[idx + 3] = o; g_cursor[idx + 3] = o; }
        if (t == 1023) carry_sm = carry + wtot[31] + sc;
        __syncthreads();
    }
    if (t == 0) g_rowptr[NN] = EE;
}

__global__ void csr_fill_kernel(const int* __restrict__ src, const int* __restrict__ dst) {
    int e = blockIdx.x * blockDim.x + threadIdx.x;
    if (e < EE) {
        int pos = atomicAdd(&g_cursor[dst[e]], 1);
        g_epos[e] = pos;
        g_srcp[pos] = src[e];
    }
}

// ---------------- node linear transforms (f32x2, 16-node tile) -----------------
template<int INDIM, int OUTDIM>
__global__ void transform_kernel(const float* __restrict__ x,
                                 const float* __restrict__ Wl, const float* __restrict__ bl,
                                 const float* __restrict__ Wr, const float* __restrict__ br,
                                 float* __restrict__ xl, float* __restrict__ xr) {
    __shared__ float xs[INDIM * 18];   // transposed: xs[k*18 + n], node-pairs adjacent
    int node0 = blockIdx.x * 16;
    int t = threadIdx.x;               // output channel
    for (int idx = t; idx < 16 * INDIM; idx += OUTDIM) {
        int n = idx / INDIM, k = idx - n * INDIM;
        xs[k * 18 + n] = x[(node0 + n) * INDIM + k];
    }
    __syncthreads();
    unsigned long long accl[8], accr[8];
    #pragma unroll
    for (int p = 0; p < 8; p++) { accl[p] = 0ull; accr[p] = 0ull; }
    #pragma unroll 4
    for (int k = 0; k < INDIM; k++) {
        float wl = Wl[k * OUTDIM + t];
        float wr = Wr[k * OUTDIM + t];
        unsigned long long wld = pack2(wl, wl), wrd = pack2(wr, wr);
        #pragma unroll
        for (int p = 0; p < 8; p++) {
            unsigned long long bp = *(const unsigned long long*)&xs[k * 18 + 2 * p];
            fma2(accl[p], bp, wld);
            fma2(accr[p], bp, wrd);
        }
    }
    float blv = bl[t], brv = br[t];
    #pragma unroll
    for (int p = 0; p < 8; p++) {
        float lo, hi;
        unpack2(accl[p], lo, hi);
        xl[(node0 + 2 * p) * OUTDIM + t]     = lo + blv;
        xl[(node0 + 2 * p + 1) * OUTDIM + t] = hi + blv;
        unpack2(accr[p], lo, hi);
        xr[(node0 + 2 * p) * OUTDIM + t]     = lo + brv;
        xr[(node0 + 2 * p + 1) * OUTDIM + t] = hi + brv;
    }
}

// ---------------- layer-1 edge logits (f32x2, 8 edges/warp) ---------------------
__global__ void edge_logits1_kernel(const int* __restrict__ src, const int* __restrict__ dst,
                                    const float* __restrict__ ea,
                                    const float* __restrict__ We, const float* __restrict__ att) {
    __shared__ float2 wed[ED * HCD];   // 32 KB: (w,w) dup pairs
    __shared__ float  eat[ED * 66];    // 64 edges, transposed, pad 66
    __shared__ float  att_sm[HCD];
    int t = threadIdx.x;
    for (int i = t; i < ED * HCD; i += 256) { float v = We[i]; wed[i] = make_float2(v, v); }
    if (t < HCD) att_sm[t] = att[t];
    int eb0 = blockIdx.x * 64;
    for (int i = t; i < 64 * ED; i += 256) {
        int j = i >> 5, k = i & 31;
        eat[k * 66 + j] = ea[(eb0 + j) * ED + k];
    }
    __syncthreads();

    int lane = t & 31, w = t >> 5;
    int ebase = eb0 + w * 8;
    int lb = w * 8;
    int c0 = 4 * lane;

    unsigned long long acc[4][4];       // [channel][edge-pair]
    #pragma unroll
    for (int c = 0; c < 4; c++)
        #pragma unroll
        for (int p = 0; p < 4; p++) acc[c][p] = 0ull;

    #pragma unroll 4
    for (int k = 0; k < ED; k++) {
        const unsigned long long* wp = (const unsigned long long*)&wed[k * HCD + c0];
        ulonglong2 w01 = *(const ulonglong2*)(wp);
        ulonglong2 w23 = *(const ulonglong2*)(wp + 2);
        unsigned long long b0 = *(const unsigned long long*)&eat[k * 66 + lb];
        unsigned long long b1 = *(const unsigned long long*)&eat[k * 66 + lb + 2];
        unsigned long long b2 = *(const unsigned long long*)&eat[k * 66 + lb + 4];
        unsigned long long b3 = *(const unsigned long long*)&eat[k * 66 + lb + 6];
        fma2(acc[0][0], b0, w01.x); fma2(acc[0][1], b1, w01.x);
        fma2(acc[0][2], b2, w01.x); fma2(acc[0][3], b3, w01.x);
        fma2(acc[1][0], b0, w01.y); fma2(acc[1][1], b1, w01.y);
        fma2(acc[1][2], b2, w01.y); fma2(acc[1][3], b3, w01.y);
        fma2(acc[2][0], b0, w23.x); fma2(acc[2][1], b1, w23.x);
        fma2(acc[2][2], b2, w23.x); fma2(acc[2][3], b3, w23.x);
        fma2(acc[3][0], b0, w23.y); fma2(acc[3][1], b1, w23.y);
        fma2(acc[3][2], b2, w23.y); fma2(acc[3][3], b3, w23.y);
    }

    float4 av = *(const float4*)&att_sm[c0];
    #pragma unroll
    for (int p = 0; p < 4; p++) {
        float v0l, v0h, v1l, v1h, v2l, v2h, v3l, v3h;
        unpack2(acc[0][p], v0l, v0h);
        unpack2(acc[1][p], v1l, v1h);
        unpack2(acc[2][p], v2l, v2h);
        unpack2(acc[3][p], v3l, v3h);
        #pragma unroll
        for (int q = 0; q < 2; q++) {
            int e = ebase + 2 * p + q;
            float e0 = q ? v0h : v0l;
            float e1 = q ? v1h : v1l;
            float e2 = q ? v2h : v2l;
            float e3 = q ? v3h : v3l;
            int s = src[e], d = dst[e];
            float4 xlv = *(const float4*)&g_xl1[s * HCD + c0];
            float4 xrv = *(const float4*)&g_xr1[d * HCD + c0];
            float psum = lrelu(e0 + xlv.x + xrv.x) * av.x
                       + lrelu(e1 + xlv.y + xrv.y) * av.y
                       + lrelu(e2 + xlv.z + xrv.z) * av.z
                       + lrelu(e3 + xlv.w + xrv.w) * av.w;
            psum += __shfl_xor_sync(0xffffffffu, psum, 1);
            psum += __shfl_xor_sync(0xffffffffu, psum, 2);
            psum += __shfl_xor_sync(0xffffffffu, psum, 4);
            if ((lane & 7) == 0) {
                int pe = g_epos[e];
                g_a1p[pe * HEADS + (lane >> 3)] = psum;
            }
        }
    }
}

// ---------------- layer-1 softmax + aggregate + bias + elu ----------------------
__global__ void aggregate1_kernel(const float* __restrict__ bias) {
    int i = (blockIdx.x * blockDim.x + threadIdx.x) >> 5;
    int lane = threadIdx.x & 31;
    if (i >= NN) return;
    int start = g_rowptr[i], end = g_rowptr[i + 1];

    int hm = lane & 3;
    float m = -INFINITY;
    for (int j = start + (lane >> 2); j < end; j += 8)
        m = fmaxf(m, g_a1p[j * HEADS + hm]);
    m = fmaxf(m, __shfl_xor_sync(0xffffffffu, m, 4));
    m = fmaxf(m, __shfl_xor_sync(0xffffffffu, m, 8));
    m = fmaxf(m, __shfl_xor_sync(0xffffffffu, m, 16));
    int myh = lane >> 3;
    float mh = __shfl_sync(0xffffffffu, m, myh);

    float den = 0.f;
    unsigned long long a01 = 0ull, a23 = 0ull;
    int c0 = 4 * lane;
    for (int j = start; j < end; j++) {
        float wv = __expf(g_a1p[j * HEADS + myh] - mh);
        int s = g_srcp[j];
        ulonglong2 xlp = *(const ulonglong2*)&g_xl1[s * HCD + c0];
        unsigned long long wd = pack2(wv, wv);
        fma2(a01, xlp.x, wd);
        fma2(a23, xlp.y, wd);
        den += wv;
    }
    float inv = 1.f / (den + 1e-16f);
    float4 bv = *(const float4*)&bias[c0];
    float o0, o1, o2, o3;
    unpack2(a01, o0, o1);
    unpack2(a23, o2, o3);
    o0 = o0 * inv + bv.x; o1 = o1 * inv + bv.y;
    o2 = o2 * inv + bv.z; o3 = o3 * inv + bv.w;
    o0 = o0 > 0.f ? o0 : expm1f(o0);
    o1 = o1 > 0.f ? o1 : expm1f(o1);
    o2 = o2 > 0.f ? o2 : expm1f(o2);
    o3 = o3 > 0.f ? o3 : expm1f(o3);
    *(float4*)&g_h[i * HCD + c0] = make_float4(o0, o1, o2, o3);
}

// ---------------- layer-2 edge logits (f32x2, 8 edges/warp) ---------------------
__global__ void edge_logits2_kernel(const int* __restrict__ src, const int* __restrict__ dst,
                                    const float* __restrict__ ea,
                                    const float* __restrict__ We, const float* __restrict__ att) {
    __shared__ float2 wed[ED * OUTC];  // 16 KB dup pairs
    __shared__ float  eat[ED * 66];
    __shared__ float  att_sm[OUTC];
    int t = threadIdx.x;
    for (int i = t; i < ED * OUTC; i += 256) { float v = We[i]; wed[i] = make_float2(v, v); }
    if (t < OUTC) att_sm[t] = att[t];
    int eb0 = blockIdx.x * 64;
    for (int i = t; i < 64 * ED; i += 256) {
        int j = i >> 5, k = i & 31;
        eat[k * 66 + j] = ea[(eb0 + j) * ED + k];
    }
    __syncthreads();

    int lane = t & 31, w = t >> 5;
    int ebase = eb0 + w * 8;
    int lb = w * 8;
    int c0 = 2 * lane;

    unsigned long long acc[2][4];
    #pragma unroll
    for (int c = 0; c < 2; c++)
        #pragma unroll
        for (int p = 0; p < 4; p++) acc[c][p] = 0ull;

    #pragma unroll 4
    for (int k = 0; k < ED; k++) {
        ulonglong2 wp = *(const ulonglong2*)&wed[k * OUTC + c0];
        unsigned long long b0 = *(const unsigned long long*)&eat[k * 66 + lb];
        unsigned long long b1 = *(const unsigned long long*)&eat[k * 66 + lb + 2];
        unsigned long long b2 = *(const unsigned long long*)&eat[k * 66 + lb + 4];
        unsigned long long b3 = *(const unsigned long long*)&eat[k * 66 + lb + 6];
        fma2(acc[0][0], b0, wp.x); fma2(acc[0][1], b1, wp.x);
        fma2(acc[0][2], b2, wp.x); fma2(acc[0][3], b3, wp.x);
        fma2(acc[1][0], b0, wp.y); fma2(acc[1][1], b1, wp.y);
        fma2(acc[1][2], b2, wp.y); fma2(acc[1][3], b3, wp.y);
    }

    float2 av = *(const float2*)&att_sm[c0];
    #pragma unroll
    for (int p = 0; p < 4; p++) {
        float v0l, v0h, v1l, v1h;
        unpack2(acc[0][p], v0l, v0h);
        unpack2(acc[1][p], v1l, v1h);
        #pragma unroll
        for (int q = 0; q < 2; q++) {
            int e = ebase + 2 * p + q;
            float e0 = q ? v0h : v0l;
            float e1 = q ? v1h : v1l;
            int s = src[e], d = dst[e];
            float2 xlv = *(const float2*)&g_xl2[s * OUTC + c0];
            float2 xrv = *(const float2*)&g_xr2[d * OUTC + c0];
            float psum = lrelu(e0 + xlv.x + xrv.x) * av.x
                       + lrelu(e1 + xlv.y + xrv.y) * av.y;
            psum += __shfl_xor_sync(0xffffffffu, psum, 1);
            psum += __shfl_xor_sync(0xffffffffu, psum, 2);
            psum += __shfl_xor_sync(0xffffffffu, psum, 4);
            psum += __shfl_xor_sync(0xffffffffu, psum, 8);
            psum += __shfl_xor_sync(0xffffffffu, psum, 16);
            if (lane == 0) g_a2p[g_epos[e]] = psum;
        }
    }
}

// ---------------- layer-2 softmax + aggregate + bias ----------------------------
__global__ void aggregate2_kernel(const float* __restrict__ bias, float* __restrict__ out) {
    int i = (blockIdx.x * blockDim.x + threadIdx.x) >> 5;
    int lane = threadIdx.x & 31;
    if (i >= NN) return;
    int start = g_rowptr[i], end = g_rowptr[i + 1];

    float m = -INFINITY;
    for (int j = start + lane; j < end; j += 32)
        m = fmaxf(m, g_a2p[j]);
    m = fmaxf(m, __shfl_xor_sync(0xffffffffu, m, 1));
    m = fmaxf(m, __shfl_xor_sync(0xffffffffu, m, 2));
    m = fmaxf(m, __shfl_xor_sync(0xffffffffu, m, 4));
    m = fmaxf(m, __shfl_xor_sync(0xffffffffu, m, 8));
    m = fmaxf(m, __shfl_xor_sync(0xffffffffu, m, 16));

    float den = 0.f;
    unsigned long long a01 = 0ull;
    int c0 = 2 * lane;
    for (int j = start; j < end; j++) {
        float wv = __expf(g_a2p[j] - m);
        int s = g_srcp[j];
        unsigned long long xlp = *(const unsigned long long*)&g_xl2[s * OUTC + c0];
        fma2(a01, xlp, pack2(wv, wv));
        den += wv;
    }
    float inv = 1.f / (den + 1e-16f);
    float o0, o1;
    unpack2(a01, o0, o1);
    o0 = o0 * inv + bias[c0];
    o1 = o1 * inv + bias[c0 + 1];
    *(float2*)&out[i * OUTC + c0] = make_float2(o0, o1);
}

// ---------------- host launcher ------------------------------------------------
extern "C" void kernel_launch(void* const* d_in, const int* in_sizes, int n_in,
                              void* d_out, int out_size) {
    const float* x    = (const float*)d_in[0];
    const int*   ei   = (const int*)  d_in[1];
    const float* ea   = (const float*)d_in[2];
    const float* Wl1  = (const float*)d_in[3];
    const float* bl1  = (const float*)d_in[4];
    const float* Wr1  = (const float*)d_in[5];
    const float* br1  = (const float*)d_in[6];
    const float* We1  = (const float*)d_in[7];
    const float* att1 = (const float*)d_in[8];
    const float* bias1= (const float*)d_in[9];
    const float* Wl2  = (const float*)d_in[10];
    const float* bl2  = (const float*)d_in[11];
    const float* Wr2  = (const float*)d_in[12];
    const float* br2  = (const float*)d_in[13];
    const float* We2  = (const float*)d_in[14];
    const float* att2 = (const float*)d_in[15];
    const float* bias2= (const float*)d_in[16];

    const int* src = ei;
    const int* dst = ei + EE;

    void *p_xl1, *p_xr1, *p_h, *p_xl2, *p_xr2, *p_deg;
    cudaGetSymbolAddress(&p_xl1, g_xl1);
    cudaGetSymbolAddress(&p_xr1, g_xr1);
    cudaGetSymbolAddress(&p_h,   g_h);
    cudaGetSymbolAddress(&p_xl2, g_xl2);
    cudaGetSymbolAddress(&p_xr2, g_xr2);
    cudaGetSymbolAddress(&p_deg, g_deg);

    // CSR by dst
    cudaMemsetAsync(p_deg, 0, NN * sizeof(int));
    csr_count_kernel<<<(EE + 255) / 256, 256>>>(dst);
    scan_kernel<<<1, 1024>>>();
    csr_fill_kernel<<<(EE + 255) / 256, 256>>>(src, dst);

    // layer 1
    transform_kernel<INC, HCD><<<NN / 16, HCD>>>(x, Wl1, bl1, Wr1, br1,
                                                 (float*)p_xl1, (float*)p_xr1);
    edge_logits1_kernel<<<EE / 64, 256>>>(src, dst, ea, We1, att1);
    aggregate1_kernel<<<NN / 8, 256>>>(bias1);

    // layer 2
    transform_kernel<HCD, OUTC><<<NN / 16, OUTC>>>((const float*)p_h, Wl2, bl2, Wr2, br2,
                                                   (float*)p_xl2, (float*)p_xr2);
    edge_logits2_kernel<<<EE / 64, 256>>>(src, dst, ea, We2, att2);
    aggregate2_kernel<<<NN / 8, 256>>>(bias2, (float*)d_out);
}

// round 3
// speedup vs baseline: 1.0109x; 1.0109x over previous
#include <cuda_runtime.h>
#include <math.h>

#define NN 50000
#define EE 800000
#define INC 128
#define HCD 128
#define HEADS 4
#define OUTC 64
#define ED 32
#define NEG 0.2f

// ---------------- scratch (device globals) ------------------------------------
__device__ float g_xl1[NN * HCD];
__device__ float g_xr1[NN * HCD];
__device__ float g_h  [NN * HCD];
__device__ float g_xl2[NN * OUTC];
__device__ float g_xr2[NN * OUTC];
__device__ float g_a1p[EE * HEADS];   // logits layer1, CSR-permuted, [pos][head]
__device__ float g_a2p[EE];           // logits layer2, CSR-permuted
__device__ int   g_deg[NN];
__device__ int   g_rowptr[NN + 1];
__device__ int   g_cursor[NN];
__device__ int   g_epos[EE];          // edge -> CSR slot
__device__ int   g_srcp[EE];          // CSR slot -> src node

// ---------------- helpers -------------------------------------------------------
__device__ __forceinline__ unsigned tf32_of(float f) {
    unsigned r;
    asm("cvt.rna.tf32.f32 %0, %1;" : "=r"(r) : "f"(f));
    return r;
}
__device__ __forceinline__ void mma_tf32(float* d,
                                         unsigned a0, unsigned a1, unsigned a2, unsigned a3,
                                         unsigned b0, unsigned b1) {
    asm volatile(
        "mma.sync.aligned.m16n8k8.row.col.f32.tf32.tf32.f32 "
        "{%0,%1,%2,%3}, {%4,%5,%6,%7}, {%8,%9}, {%0,%1,%2,%3};"
        : "+f"(d[0]), "+f"(d[1]), "+f"(d[2]), "+f"(d[3])
        : "r"(a0), "r"(a1), "r"(a2), "r"(a3), "r"(b0), "r"(b1));
}
__device__ __forceinline__ float lrelu(float x) { return x > 0.f ? x : NEG * x; }

// ---------------- CSR build -----------------------------------------------------
__global__ void csr_count_kernel(const int* __restrict__ dst) {
    int e = blockIdx.x * blockDim.x + threadIdx.x;
    if (e < EE) atomicAdd(&g_deg[dst[e]], 1);
}

__global__ void scan_kernel() {
    __shared__ int wtot[32];
    __shared__ int carry_sm;
    int t = threadIdx.x, lane = t & 31, wid = t >> 5;
    if (t == 0) carry_sm = 0;
    __syncthreads();
    for (int base = 0; base < NN; base += 4096) {
        int carry = carry_sm;
        int idx = base + t * 4;
        int4 v = make_int4(0, 0, 0, 0);
        if (idx + 3 < NN) v = *(const int4*)&g_deg[idx];
        else {
            if (idx     < NN) v.x = g_deg[idx];
            if (idx + 1 < NN) v.y = g_deg[idx + 1];
            if (idx + 2 < NN) v.z = g_deg[idx + 2];
        }
        int s1 = v.x + v.y, s2 = s1 + v.z, tsum = s2 + v.w;
        int sc = tsum;
        #pragma unroll
        for (int off = 1; off < 32; off <<= 1) {
            int u = __shfl_up_sync(0xffffffffu, sc, off);
            if (lane >= off) sc += u;
        }
        if (lane == 31) wtot[wid] = sc;
        __syncthreads();
        if (wid == 0) {
            int wv = wtot[lane];
            int ws = wv;
            #pragma unroll
            for (int off = 1; off < 32; off <<= 1) {
                int u = __shfl_up_sync(0xffffffffu, ws, off);
                if (lane >= off) ws += u;
            }
            wtot[lane] = ws - wv;
        }
        __syncthreads();
        int off0 = carry + wtot[wid] + (sc - tsum);
        if (idx     < NN) { g_rowptr[idx]     = off0;        g_cursor[idx]     = off0; }
        if (idx + 1 < NN) { int o = off0 + v.x; g_rowptr[idx + 1] = o; g_cursor[idx + 1] = o; }
        if (idx + 2 < NN) { int o = off0 + s1;  g_rowptr[idx + 2] = o; g_cursor[idx + 2] = o; }
        if (idx + 3 < NN) { int o = off0 + s2;  g_rowptr[idx + 3] = o; g_cursor[idx + 3] = o; }
        if (t == 1023) carry_sm = carry + wtot[31] + sc;
        __syncthreads();
    }
    if (t == 0) g_rowptr[NN] = EE;
}

__global__ void csr_fill_kernel(const int* __restrict__ src, const int* __restrict__ dst) {
    int e = blockIdx.x * blockDim.x + threadIdx.x;
    if (e < EE) {
        int pos = atomicAdd(&g_cursor[dst[e]], 1);
        g_epos[e] = pos;
        g_srcp[pos] = src[e];
    }
}

// ---------------- node transform via tf32 MMA -----------------------------------
// Block: 256 thr = 8 warps. 32 nodes/block. Warp w: node-half (w>>2)*16,
// col-group (w&3) of the combined [Wl|Wr] output (2*OUTDIM cols).
template<int OUTDIM>
__global__ __launch_bounds__(256) void transform_mma_kernel(
    const float* __restrict__ x,
    const float* __restrict__ Wl, const float* __restrict__ bl,
    const float* __restrict__ Wr, const float* __restrict__ br,
    float* __restrict__ xl, float* __restrict__ xr) {
    constexpr int K = 128;
    constexpr int NT = OUTDIM / 16;       // n-tiles per warp
    constexpr int WCOLS = OUTDIM / 2;     // cols per warp
    constexpr int TC = 2 * OUTDIM;        // total combined cols
    constexpr int WSTR = TC + 8;          // padded smem stride (shift-8 banks)
    __shared__ unsigned xs[32 * 132];
    __shared__ unsigned wsm[16 * WSTR];

    int tid = threadIdx.x;
    int node0 = blockIdx.x * 32;
    for (int idx = tid; idx < 32 * K; idx += 256) {
        int n = idx >> 7, k = idx & 127;
        float v = (node0 + n < NN) ? x[(node0 + n) * K + k] : 0.f;
        xs[n * 132 + k] = tf32_of(v);
    }
    int w = tid >> 5, lane = tid & 31, g = lane >> 2, t4 = lane & 3;
    int nh = w >> 2, cg = w & 3;
    int colbase = cg * WCOLS;

    float d[NT][4];
    #pragma unroll
    for (int nt = 0; nt < NT; nt++)
        #pragma unroll
        for (int i = 0; i < 4; i++) d[nt][i] = 0.f;

    for (int kc = 0; kc < 8; kc++) {
        __syncthreads();
        for (int idx = tid; idx < 16 * TC; idx += 256) {
            int kr = idx / TC, c = idx % TC;
            int kg = kc * 16 + kr;
            float v = (c < OUTDIM) ? Wl[kg * OUTDIM + c] : Wr[kg * OUTDIM + c - OUTDIM];
            wsm[kr * WSTR + c] = tf32_of(v);
        }
        __syncthreads();
        #pragma unroll
        for (int kt = 0; kt < 2; kt++) {
            int kb = kt * 8;
            int ab = (nh * 16 + g) * 132 + kc * 16 + kb + t4;
            unsigned a0 = xs[ab], a1 = xs[ab + 8 * 132];
            unsigned a2 = xs[ab + 4], a3 = xs[ab + 8 * 132 + 4];
            #pragma unroll
            for (int nt = 0; nt < NT; nt++) {
                unsigned b0 = wsm[(kb + t4) * WSTR + colbase + nt * 8 + g];
                unsigned b1 = wsm[(kb + t4 + 4) * WSTR + colbase + nt * 8 + g];
                mma_tf32(d[nt], a0, a1, a2, a3, b0, b1);
            }
        }
    }

    #pragma unroll
    for (int nt = 0; nt < NT; nt++) {
        int c = colbase + nt * 8 + t4 * 2;
        const float* bp; float* op; int cc;
        if (c < OUTDIM) { cc = c; bp = bl; op = xl; }
        else            { cc = c - OUTDIM; bp = br; op = xr; }
        float2 bv = *(const float2*)&bp[cc];
        int n0v = node0 + nh * 16 + g;
        if (n0v < NN)
            *(float2*)&op[n0v * OUTDIM + cc] = make_float2(d[nt][0] + bv.x, d[nt][1] + bv.y);
        int n1v = n0v + 8;
        if (n1v < NN)
            *(float2*)&op[n1v * OUTDIM + cc] = make_float2(d[nt][2] + bv.x, d[nt][3] + bv.y);
    }
}

// ---------------- layer-1 edge logits via tf32 MMA -------------------------------
// Block 256 thr = 8 warps x 16 edges = 128 edges/block. Warp tile: [16 edges x 128 ch].
__global__ __launch_bounds__(256, 2) void edge_logits1_mma(
    const int* __restrict__ src, const int* __restrict__ dst,
    const float* __restrict__ ea,
    const float* __restrict__ We, const float* __restrict__ att) {
    __shared__ unsigned eat[128 * 36];
    __shared__ unsigned wsm[32 * 136];
    __shared__ float att_sm[128];
    int tid = threadIdx.x;
    int eb0 = blockIdx.x * 128;
    for (int idx = tid; idx < 128 * 32; idx += 256) {
        int le = idx >> 5, k = idx & 31;
        eat[le * 36 + k] = tf32_of(ea[(eb0 + le) * 32 + k]);
    }
    for (int idx = tid; idx < 32 * 128; idx += 256) {
        int kr = idx >> 7, c = idx & 127;
        wsm[kr * 136 + c] = tf32_of(We[idx]);
    }
    if (tid < 128) att_sm[tid] = att[tid];
    __syncthreads();

    int w = tid >> 5, lane = tid & 31, g = lane >> 2, t4 = lane & 3;
    float d[16][4];
    #pragma unroll
    for (int nt = 0; nt < 16; nt++)
        #pragma unroll
        for (int i = 0; i < 4; i++) d[nt][i] = 0.f;

    #pragma unroll
    for (int kt = 0; kt < 4; kt++) {
        int ab = (w * 16 + g) * 36 + kt * 8 + t4;
        unsigned a0 = eat[ab], a1 = eat[ab + 8 * 36];
        unsigned a2 = eat[ab + 4], a3 = eat[ab + 8 * 36 + 4];
        #pragma unroll
        for (int nt = 0; nt < 16; nt++) {
            unsigned b0 = wsm[(kt * 8 + t4) * 136 + nt * 8 + g];
            unsigned b1 = wsm[(kt * 8 + t4 + 4) * 136 + nt * 8 + g];
            mma_tf32(d[nt], a0, a1, a2, a3, b0, b1);
        }
    }

    int ebase = eb0 + w * 16;
    #pragma unroll
    for (int rsel = 0; rsel < 2; rsel++) {
        int e = ebase + g + 8 * rsel;
        int s = src[e], dd = dst[e];
        const float* xlr = g_xl1 + s * HCD;
        const float* xrr = g_xr1 + dd * HCD;
        float ph0 = 0.f, ph1 = 0.f, ph2 = 0.f, ph3 = 0.f;
        #pragma unroll
        for (int nt = 0; nt < 16; nt++) {
            int c = nt * 8 + t4 * 2;
            float2 xlv = *(const float2*)&xlr[c];
            float2 xrv = *(const float2*)&xrr[c];
            float2 atv = *(const float2*)&att_sm[c];
            float v0 = d[nt][rsel * 2]     + xlv.x + xrv.x;
            float v1 = d[nt][rsel * 2 + 1] + xlv.y + xrv.y;
            float p = lrelu(v0) * atv.x + lrelu(v1) * atv.y;
            if      (nt < 4)  ph0 += p;
            else if (nt < 8)  ph1 += p;
            else if (nt < 12) ph2 += p;
            else              ph3 += p;
        }
        ph0 += __shfl_xor_sync(0xffffffffu, ph0, 1); ph0 += __shfl_xor_sync(0xffffffffu, ph0, 2);
        ph1 += __shfl_xor_sync(0xffffffffu, ph1, 1); ph1 += __shfl_xor_sync(0xffffffffu, ph1, 2);
        ph2 += __shfl_xor_sync(0xffffffffu, ph2, 1); ph2 += __shfl_xor_sync(0xffffffffu, ph2, 2);
        ph3 += __shfl_xor_sync(0xffffffffu, ph3, 1); ph3 += __shfl_xor_sync(0xffffffffu, ph3, 2);
        int pe = g_epos[e];
        float myv = (t4 == 0) ? ph0 : (t4 == 1) ? ph1 : (t4 == 2) ? ph2 : ph3;
        g_a1p[pe * HEADS + t4] = myv;
    }
}

// ---------------- layer-2 edge logits via tf32 MMA -------------------------------
__global__ __launch_bounds__(256, 2) void edge_logits2_mma(
    const int* __restrict__ src, const int* __restrict__ dst,
    const float* __restrict__ ea,
    const float* __restrict__ We, const float* __restrict__ att) {
    __shared__ unsigned eat[128 * 36];
    __shared__ unsigned wsm[32 * 72];
    __shared__ float att_sm[64];
    int tid = threadIdx.x;
    int eb0 = blockIdx.x * 128;
    for (int idx = tid; idx < 128 * 32; idx += 256) {
        int le = idx >> 5, k = idx & 31;
        eat[le * 36 + k] = tf32_of(ea[(eb0 + le) * 32 + k]);
    }
    for (int idx = tid; idx < 32 * 64; idx += 256) {
        int kr = idx >> 6, c = idx & 63;
        wsm[kr * 72 + c] = tf32_of(We[idx]);
    }
    if (tid < 64) att_sm[tid] = att[tid];
    __syncthreads();

    int w = tid >> 5, lane = tid & 31, g = lane >> 2, t4 = lane & 3;
    float d[8][4];
    #pragma unroll
    for (int nt = 0; nt < 8; nt++)
        #pragma unroll
        for (int i = 0; i < 4; i++) d[nt][i] = 0.f;

    #pragma unroll
    for (int kt = 0; kt < 4; kt++) {
        int ab = (w * 16 + g) * 36 + kt * 8 + t4;
        unsigned a0 = eat[ab], a1 = eat[ab + 8 * 36];
        unsigned a2 = eat[ab + 4], a3 = eat[ab + 8 * 36 + 4];
        #pragma unroll
        for (int nt = 0; nt < 8; nt++) {
            unsigned b0 = wsm[(kt * 8 + t4) * 72 + nt * 8 + g];
            unsigned b1 = wsm[(kt * 8 + t4 + 4) * 72 + nt * 8 + g];
            mma_tf32(d[nt], a0, a1, a2, a3, b0, b1);
        }
    }

    int ebase = eb0 + w * 16;
    #pragma unroll
    for (int rsel = 0; rsel < 2; rsel++) {
        int e = ebase + g + 8 * rsel;
        int s = src[e], dd = dst[e];
        const float* xlr = g_xl2 + s * OUTC;
        const float* xrr = g_xr2 + dd * OUTC;
        float ps = 0.f;
        #pragma unroll
        for (int nt = 0; nt < 8; nt++) {
            int c = nt * 8 + t4 * 2;
            float2 xlv = *(const float2*)&xlr[c];
            float2 xrv = *(const float2*)&xrr[c];
            float2 atv = *(const float2*)&att_sm[c];
            float v0 = d[nt][rsel * 2]     + xlv.x + xrv.x;
            float v1 = d[nt][rsel * 2 + 1] + xlv.y + xrv.y;
            ps += lrelu(v0) * atv.x + lrelu(v1) * atv.y;
        }
        ps += __shfl_xor_sync(0xffffffffu, ps, 1);
        ps += __shfl_xor_sync(0xffffffffu, ps, 2);
        if (t4 == 0) g_a2p[g_epos[e]] = ps;
    }
}

// ---------------- layer-1 softmax + aggregate + bias + elu ------------------------
__global__ void aggregate1_kernel(const float* __restrict__ bias) {
    int i = (blockIdx.x * blockDim.x + threadIdx.x) >> 5;
    int lane = threadIdx.x & 31;
    if (i >= NN) return;
    int start = g_rowptr[i], end = g_rowptr[i + 1];

    int hm = lane & 3;
    float m = -INFINITY;
    for (int j = start + (lane >> 2); j < end; j += 8)
        m = fmaxf(m, g_a1p[j * HEADS + hm]);
    m = fmaxf(m, __shfl_xor_sync(0xffffffffu, m, 4));
    m = fmaxf(m, __shfl_xor_sync(0xffffffffu, m, 8));
    m = fmaxf(m, __shfl_xor_sync(0xffffffffu, m, 16));
    int myh = lane >> 3;
    float mh = __shfl_sync(0xffffffffu, m, myh);

    float den = 0.f;
    float a0 = 0.f, a1 = 0.f, a2 = 0.f, a3 = 0.f;
    int c0 = 4 * lane;
    for (int j = start; j < end; j++) {
        float wv = __expf(g_a1p[j * HEADS + myh] - mh);
        int s = g_srcp[j];
        float4 xlv = *(const float4*)&g_xl1[s * HCD + c0];
        den += wv;
        a0 = fmaf(wv, xlv.x, a0);
        a1 = fmaf(wv, xlv.y, a1);
        a2 = fmaf(wv, xlv.z, a2);
        a3 = fmaf(wv, xlv.w, a3);
    }
    float inv = 1.f / (den + 1e-16f);
    float4 bv = *(const float4*)&bias[c0];
    float o0 = a0 * inv + bv.x;
    float o1 = a1 * inv + bv.y;
    float o2 = a2 * inv + bv.z;
    float o3 = a3 * inv + bv.w;
    o0 = o0 > 0.f ? o0 : expm1f(o0);
    o1 = o1 > 0.f ? o1 : expm1f(o1);
    o2 = o2 > 0.f ? o2 : expm1f(o2);
    o3 = o3 > 0.f ? o3 : expm1f(o3);
    *(float4*)&g_h[i * HCD + c0] = make_float4(o0, o1, o2, o3);
}

// ---------------- layer-2 softmax + aggregate + bias ------------------------------
__global__ void aggregate2_kernel(const float* __restrict__ bias, float* __restrict__ out) {
    int i = (blockIdx.x * blockDim.x + threadIdx.x) >> 5;
    int lane = threadIdx.x & 31;
    if (i >= NN) return;
    int start = g_rowptr[i], end = g_rowptr[i + 1];

    float m = -INFINITY;
    for (int j = start + lane; j < end; j += 32)
        m = fmaxf(m, g_a2p[j]);
    m = fmaxf(m, __shfl_xor_sync(0xffffffffu, m, 1));
    m = fmaxf(m, __shfl_xor_sync(0xffffffffu, m, 2));
    m = fmaxf(m, __shfl_xor_sync(0xffffffffu, m, 4));
    m = fmaxf(m, __shfl_xor_sync(0xffffffffu, m, 8));
    m = fmaxf(m, __shfl_xor_sync(0xffffffffu, m, 16));

    float den = 0.f;
    float a0 = 0.f, a1 = 0.f;
    int c0 = 2 * lane;
    for (int j = start; j < end; j++) {
        float wv = __expf(g_a2p[j] - m);
        int s = g_srcp[j];
        float2 xlv = *(const float2*)&g_xl2[s * OUTC + c0];
        den += wv;
        a0 = fmaf(wv, xlv.x, a0);
        a1 = fmaf(wv, xlv.y, a1);
    }
    float inv = 1.f / (den + 1e-16f);
    float o0 = a0 * inv + bias[c0];
    float o1 = a1 * inv + bias[c0 + 1];
    *(float2*)&out[i * OUTC + c0] = make_float2(o0, o1);
}

// ---------------- host launcher ---------------------------------------------------
extern "C" void kernel_launch(void* const* d_in, const int* in_sizes, int n_in,
                              void* d_out, int out_size) {
    const float* x    = (const float*)d_in[0];
    const int*   ei   = (const int*)  d_in[1];
    const float* ea   = (const float*)d_in[2];
    const float* Wl1  = (const float*)d_in[3];
    const float* bl1  = (const float*)d_in[4];
    const float* Wr1  = (const float*)d_in[5];
    const float* br1  = (const float*)d_in[6];
    const float* We1  = (const float*)d_in[7];
    const float* att1 = (const float*)d_in[8];
    const float* bias1= (const float*)d_in[9];
    const float* Wl2  = (const float*)d_in[10];
    const float* bl2  = (const float*)d_in[11];
    const float* Wr2  = (const float*)d_in[12];
    const float* br2  = (const float*)d_in[13];
    const float* We2  = (const float*)d_in[14];
    const float* att2 = (const float*)d_in[15];
    const float* bias2= (const float*)d_in[16];

    const int* src = ei;
    const int* dst = ei + EE;

    void *p_xl1, *p_xr1, *p_h, *p_xl2, *p_xr2, *p_deg;
    cudaGetSymbolAddress(&p_xl1, g_xl1);
    cudaGetSymbolAddress(&p_xr1, g_xr1);
    cudaGetSymbolAddress(&p_h,   g_h);
    cudaGetSymbolAddress(&p_xl2, g_xl2);
    cudaGetSymbolAddress(&p_xr2, g_xr2);
    cudaGetSymbolAddress(&p_deg, g_deg);

    // CSR by dst
    cudaMemsetAsync(p_deg, 0, NN * sizeof(int));
    csr_count_kernel<<<(EE + 255) / 256, 256>>>(dst);
    scan_kernel<<<1, 1024>>>();
    csr_fill_kernel<<<(EE + 255) / 256, 256>>>(src, dst);

    // layer 1
    transform_mma_kernel<HCD><<<(NN + 31) / 32, 256>>>(x, Wl1, bl1, Wr1, br1,
                                                       (float*)p_xl1, (float*)p_xr1);
    edge_logits1_mma<<<EE / 128, 256>>>(src, dst, ea, We1, att1);
    aggregate1_kernel<<<NN / 8, 256>>>(bias1);

    // layer 2
    transform_mma_kernel<OUTC><<<(NN + 31) / 32, 256>>>((const float*)p_h, Wl2, bl2, Wr2, br2,
                                                        (float*)p_xl2, (float*)p_xr2);
    edge_logits2_mma<<<EE / 128, 256>>>(src, dst, ea, We2, att2);
    aggregate2_kernel<<<NN / 8, 256>>>(bias2, (float*)d_out);
}

// round 4
// speedup vs baseline: 1.9437x; 1.9226x over previous
#include <cuda_runtime.h>
#include <math.h>

#define NN 50000
#define EE 800000
#define HCD 128
#define HEADS 4
#define OUTC 64
#define ED 32
#define NEG 0.2f

// ---------------- scratch (device globals) ------------------------------------
__device__ float g_xl1[NN * HCD];
__device__ float g_xr1[NN * HCD];
__device__ float g_h  [NN * HCD];
__device__ float g_xl2[NN * OUTC];
__device__ float g_xr2[NN * OUTC];
__device__ float g_a1p[EE * HEADS];
__device__ float g_a2p[EE];
__device__ int   g_deg[NN];
__device__ int   g_rowptr[NN + 1];
__device__ int   g_cursor[NN];
__device__ int   g_epos[EE];
__device__ int   g_srcp[EE];
// pre-packed tf32 B-fragments: [kt][ntg][lane]{b0,b1}
__device__ uint2 g_W1p[16 * 32 * 32];   // K=128, TC=256
__device__ uint2 g_W2p[16 * 16 * 32];   // K=128, TC=128
__device__ uint2 g_We1p[4 * 16 * 32];   // K=32,  N=128
__device__ uint2 g_We2p[4 * 8 * 32];    // K=32,  N=64

// ---------------- helpers -------------------------------------------------------
__device__ __forceinline__ unsigned tf32_of(float f) {
    unsigned r;
    asm("cvt.rna.tf32.f32 %0, %1;" : "=r"(r) : "f"(f));
    return r;
}
__device__ __forceinline__ void mma_tf32(float* d,
                                         unsigned a0, unsigned a1, unsigned a2, unsigned a3,
                                         unsigned b0, unsigned b1) {
    asm volatile(
        "mma.sync.aligned.m16n8k8.row.col.f32.tf32.tf32.f32 "
        "{%0,%1,%2,%3}, {%4,%5,%6,%7}, {%8,%9}, {%0,%1,%2,%3};"
        : "+f"(d[0]), "+f"(d[1]), "+f"(d[2]), "+f"(d[3])
        : "r"(a0), "r"(a1), "r"(a2), "r"(a3), "r"(b0), "r"(b1));
}
__device__ __forceinline__ float lrelu(float x) { return x > 0.f ? x : NEG * x; }

// ---------------- weight fragment pre-pack --------------------------------------
// one warp per (array, kt, ntg). b0 = W[kt*8+t4][ntg*8+g], b1 = W[kt*8+t4+4][...]
__global__ void prepack_kernel(const float* __restrict__ Wl1, const float* __restrict__ Wr1,
                               const float* __restrict__ Wl2, const float* __restrict__ Wr2,
                               const float* __restrict__ We1, const float* __restrict__ We2) {
    int gw = blockIdx.x * 8 + (threadIdx.x >> 5);
    int lane = threadIdx.x & 31, g = lane >> 2, t4 = lane & 3;
    // segments: W1: 512 warps (16x32), W2: 256 (16x16), We1: 64 (4x16), We2: 32 (4x8)
    if (gw < 512) {
        int kt = gw >> 5, ntg = gw & 31;
        int c = ntg * 8 + g, k0 = kt * 8 + t4;
        float v0 = (c < 128) ? Wl1[k0 * 128 + c] : Wr1[k0 * 128 + c - 128];
        float v1 = (c < 128) ? Wl1[(k0 + 4) * 128 + c] : Wr1[(k0 + 4) * 128 + c - 128];
        g_W1p[(kt * 32 + ntg) * 32 + lane] = make_uint2(tf32_of(v0), tf32_of(v1));
    } else if (gw < 768) {
        int r = gw - 512;
        int kt = r >> 4, ntg = r & 15;
        int c = ntg * 8 + g, k0 = kt * 8 + t4;
        float v0 = (c < 64) ? Wl2[k0 * 64 + c] : Wr2[k0 * 64 + c - 64];
        float v1 = (c < 64) ? Wl2[(k0 + 4) * 64 + c] : Wr2[(k0 + 4) * 64 + c - 64];
        g_W2p[(kt * 16 + ntg) * 32 + lane] = make_uint2(tf32_of(v0), tf32_of(v1));
    } else if (gw < 832) {
        int r = gw - 768;
        int kt = r >> 4, ntg = r & 15;
        int c = ntg * 8 + g, k0 = kt * 8 + t4;
        g_We1p[(kt * 16 + ntg) * 32 + lane] =
            make_uint2(tf32_of(We1[k0 * 128 + c]), tf32_of(We1[(k0 + 4) * 128 + c]));
    } else if (gw < 864) {
        int r = gw - 832;
        int kt = r >> 3, ntg = r & 7;
        int c = ntg * 8 + g, k0 = kt * 8 + t4;
        g_We2p[(kt * 8 + ntg) * 32 + lane] =
            make_uint2(tf32_of(We2[k0 * 64 + c]), tf32_of(We2[(k0 + 4) * 64 + c]));
    }
}

// ---------------- CSR build -----------------------------------------------------
__global__ void csr_count_kernel(const int* __restrict__ dst) {
    int e = blockIdx.x * blockDim.x + threadIdx.x;
    if (e < EE) atomicAdd(&g_deg[dst[e]], 1);
}

__global__ void scan_kernel() {
    __shared__ int wtot[32];
    __shared__ int carry_sm;
    int t = threadIdx.x, lane = t & 31, wid = t >> 5;
    if (t == 0) carry_sm = 0;
    __syncthreads();
    for (int base = 0; base < NN; base += 4096) {
        int carry = carry_sm;
        int idx = base + t * 4;
        int4 v = make_int4(0, 0, 0, 0);
        if (idx + 3 < NN) v = *(const int4*)&g_deg[idx];
        else {
            if (idx     < NN) v.x = g_deg[idx];
            if (idx + 1 < NN) v.y = g_deg[idx + 1];
            if (idx + 2 < NN) v.z = g_deg[idx + 2];
        }
        int s1 = v.x + v.y, s2 = s1 + v.z, tsum = s2 + v.w;
        int sc = tsum;
        #pragma unroll
        for (int off = 1; off < 32; off <<= 1) {
            int u = __shfl_up_sync(0xffffffffu, sc, off);
            if (lane >= off) sc += u;
        }
        if (lane == 31) wtot[wid] = sc;
        __syncthreads();
        if (wid == 0) {
            int wv = wtot[lane];
            int ws = wv;
            #pragma unroll
            for (int off = 1; off < 32; off <<= 1) {
                int u = __shfl_up_sync(0xffffffffu, ws, off);
                if (lane >= off) ws += u;
            }
            wtot[lane] = ws - wv;
        }
        __syncthreads();
        int off0 = carry + wtot[wid] + (sc - tsum);
        if (idx     < NN) { g_rowptr[idx]     = off0;        g_cursor[idx]     = off0; }
        if (idx + 1 < NN) { int o = off0 + v.x; g_rowptr[idx + 1] = o; g_cursor[idx + 1] = o; }
        if (idx + 2 < NN) { int o = off0 + s1;  g_rowptr[idx + 2] = o; g_cursor[idx + 2] = o; }
        if (idx + 3 < NN) { int o = off0 + s2;  g_rowptr[idx + 3] = o; g_cursor[idx + 3] = o; }
        if (t == 1023) carry_sm = carry + wtot[31] + sc;
        __syncthreads();
    }
    if (t == 0) g_rowptr[NN] = EE;
}

__global__ void csr_fill_kernel(const int* __restrict__ src, const int* __restrict__ dst) {
    int e = blockIdx.x * blockDim.x + threadIdx.x;
    if (e < EE) {
        int pos = atomicAdd(&g_cursor[dst[e]], 1);
        g_epos[e] = pos;
        g_srcp[pos] = src[e];
    }
}

// ---------------- node transform: direct-LDG tf32 MMA ---------------------------
// K=128. Block 256 thr = 8 warps as 4(m) x 2(n): warp tile 32 rows x 64 cols.
// Block tile: 128 rows x 128 cols; gridDim.y covers TC/128.
template<int OUTD, int TC>
__global__ __launch_bounds__(256) void transform_direct(
    const float* __restrict__ x, const uint2* __restrict__ Wp,
    const float* __restrict__ bl, const float* __restrict__ br,
    float* __restrict__ xl, float* __restrict__ xr) {
    constexpr int NTT = TC / 8;            // total n-tiles in Wp
    int tid = threadIdx.x;
    int w = tid >> 5, lane = tid & 31, g = lane >> 2, t4 = lane & 3;
    int mrow = w & 3, ncol = w >> 2;
    int node0 = blockIdx.x * 128 + mrow * 32;
    int ntbase = blockIdx.y * 16 + ncol * 8;   // first global n-tile for this warp

    float acc[2][8][4];
    #pragma unroll
    for (int mt = 0; mt < 2; mt++)
        #pragma unroll
        for (int nt = 0; nt < 8; nt++)
            #pragma unroll
            for (int i = 0; i < 4; i++) acc[mt][nt][i] = 0.f;

    #pragma unroll 4
    for (int kt = 0; kt < 16; kt++) {
        unsigned a[2][4];
        #pragma unroll
        for (int mt = 0; mt < 2; mt++) {
            int r0 = node0 + mt * 16 + g;
            int r1 = r0 + 8;
            if (r0 >= NN) r0 = NN - 1;
            if (r1 >= NN) r1 = NN - 1;
            const float* p0 = x + r0 * 128 + kt * 8 + t4;
            const float* p1 = x + r1 * 128 + kt * 8 + t4;
            a[mt][0] = tf32_of(__ldg(p0));
            a[mt][1] = tf32_of(__ldg(p1));
            a[mt][2] = tf32_of(__ldg(p0 + 4));
            a[mt][3] = tf32_of(__ldg(p1 + 4));
        }
        const uint2* wrow = Wp + (kt * NTT + ntbase) * 32 + lane;
        #pragma unroll
        for (int nt = 0; nt < 8; nt++) {
            uint2 b = __ldg(wrow + nt * 32);
            mma_tf32(acc[0][nt], a[0][0], a[0][1], a[0][2], a[0][3], b.x, b.y);
            mma_tf32(acc[1][nt], a[1][0], a[1][1], a[1][2], a[1][3], b.x, b.y);
        }
    }

    #pragma unroll
    for (int nt = 0; nt < 8; nt++) {
        int c = (ntbase + nt) * 8 + t4 * 2;
        const float* bp; float* op; int cc;
        if (c < OUTD) { cc = c; bp = bl; op = xl; }
        else          { cc = c - OUTD; bp = br; op = xr; }
        float2 bv = *(const float2*)&bp[cc];
        #pragma unroll
        for (int mt = 0; mt < 2; mt++) {
            int n0v = node0 + mt * 16 + g;
            if (n0v < NN)
                *(float2*)&op[n0v * OUTD + cc] =
                    make_float2(acc[mt][nt][0] + bv.x, acc[mt][nt][1] + bv.y);
            int n1v = n0v + 8;
            if (n1v < NN)
                *(float2*)&op[n1v * OUTD + cc] =
                    make_float2(acc[mt][nt][2] + bv.x, acc[mt][nt][3] + bv.y);
        }
    }
}

// ---------------- layer-1 edge logits: direct-LDG tf32 MMA ----------------------
// Block 256 = 8 warps x 16 edges. Warp: m16(edges) x n128(channels), K=32.
__global__ __launch_bounds__(256) void edge_logits1_direct(
    const int* __restrict__ src, const int* __restrict__ dst,
    const float* __restrict__ ea, const float* __restrict__ att) {
    int tid = threadIdx.x;
    int w = tid >> 5, lane = tid & 31, g = lane >> 2, t4 = lane & 3;
    int ebase = blockIdx.x * 128 + w * 16;

    float d[16][4];
    #pragma unroll
    for (int nt = 0; nt < 16; nt++)
        #pragma unroll
        for (int i = 0; i < 4; i++) d[nt][i] = 0.f;

    #pragma unroll
    for (int kt = 0; kt < 4; kt++) {
        const float* p0 = ea + (ebase + g) * 32 + kt * 8 + t4;
        const float* p1 = ea + (ebase + 8 + g) * 32 + kt * 8 + t4;
        unsigned a0 = tf32_of(__ldg(p0));
        unsigned a1 = tf32_of(__ldg(p1));
        unsigned a2 = tf32_of(__ldg(p0 + 4));
        unsigned a3 = tf32_of(__ldg(p1 + 4));
        const uint2* wrow = g_We1p + (kt * 16) * 32 + lane;
        #pragma unroll
        for (int nt = 0; nt < 16; nt++) {
            uint2 b = __ldg(wrow + nt * 32);
            mma_tf32(d[nt], a0, a1, a2, a3, b.x, b.y);
        }
    }

    #pragma unroll
    for (int rsel = 0; rsel < 2; rsel++) {
        int e = ebase + g + 8 * rsel;
        int s = src[e], dd = dst[e];
        const float* xlr = g_xl1 + s * HCD;
        const float* xrr = g_xr1 + dd * HCD;
        float ph0 = 0.f, ph1 = 0.f, ph2 = 0.f, ph3 = 0.f;
        #pragma unroll
        for (int nt = 0; nt < 16; nt++) {
            int c = nt * 8 + t4 * 2;
            float2 xlv = *(const float2*)&xlr[c];
            float2 xrv = *(const float2*)&xrr[c];
            float2 atv = *(const float2*)&att[c];
            float v0 = d[nt][rsel * 2]     + xlv.x + xrv.x;
            float v1 = d[nt][rsel * 2 + 1] + xlv.y + xrv.y;
            float p = lrelu(v0) * atv.x + lrelu(v1) * atv.y;
            if      (nt < 4)  ph0 += p;
            else if (nt < 8)  ph1 += p;
            else if (nt < 12) ph2 += p;
            else              ph3 += p;
        }
        ph0 += __shfl_xor_sync(0xffffffffu, ph0, 1); ph0 += __shfl_xor_sync(0xffffffffu, ph0, 2);
        ph1 += __shfl_xor_sync(0xffffffffu, ph1, 1); ph1 += __shfl_xor_sync(0xffffffffu, ph1, 2);
        ph2 += __shfl_xor_sync(0xffffffffu, ph2, 1); ph2 += __shfl_xor_sync(0xffffffffu, ph2, 2);
        ph3 += __shfl_xor_sync(0xffffffffu, ph3, 1); ph3 += __shfl_xor_sync(0xffffffffu, ph3, 2);
        int pe = g_epos[e];
        float myv = (t4 == 0) ? ph0 : (t4 == 1) ? ph1 : (t4 == 2) ? ph2 : ph3;
        g_a1p[pe * HEADS + t4] = myv;
    }
}

// ---------------- layer-2 edge logits: direct-LDG tf32 MMA ----------------------
__global__ __launch_bounds__(256) void edge_logits2_direct(
    const int* __restrict__ src, const int* __restrict__ dst,
    const float* __restrict__ ea, const float* __restrict__ att) {
    int tid = threadIdx.x;
    int w = tid >> 5, lane = tid & 31, g = lane >> 2, t4 = lane & 3;
    int ebase = blockIdx.x * 128 + w * 16;

    float d[8][4];
    #pragma unroll
    for (int nt = 0; nt < 8; nt++)
        #pragma unroll
        for (int i = 0; i < 4; i++) d[nt][i] = 0.f;

    #pragma unroll
    for (int kt = 0; kt < 4; kt++) {
        const float* p0 = ea + (ebase + g) * 32 + kt * 8 + t4;
        const float* p1 = ea + (ebase + 8 + g) * 32 + kt * 8 + t4;
        unsigned a0 = tf32_of(__ldg(p0));
        unsigned a1 = tf32_of(__ldg(p1));
        unsigned a2 = tf32_of(__ldg(p0 + 4));
        unsigned a3 = tf32_of(__ldg(p1 + 4));
        const uint2* wrow = g_We2p + (kt * 8) * 32 + lane;
        #pragma unroll
        for (int nt = 0; nt < 8; nt++) {
            uint2 b = __ldg(wrow + nt * 32);
            mma_tf32(d[nt], a0, a1, a2, a3, b.x, b.y);
        }
    }

    #pragma unroll
    for (int rsel = 0; rsel < 2; rsel++) {
        int e = ebase + g + 8 * rsel;
        int s = src[e], dd = dst[e];
        const float* xlr = g_xl2 + s * OUTC;
        const float* xrr = g_xr2 + dd * OUTC;
        float ps = 0.f;
        #pragma unroll
        for (int nt = 0; nt < 8; nt++) {
            int c = nt * 8 + t4 * 2;
            float2 xlv = *(const float2*)&xlr[c];
            float2 xrv = *(const float2*)&xrr[c];
            float2 atv = *(const float2*)&att[c];
            float v0 = d[nt][rsel * 2]     + xlv.x + xrv.x;
            float v1 = d[nt][rsel * 2 + 1] + xlv.y + xrv.y;
            ps += lrelu(v0) * atv.x + lrelu(v1) * atv.y;
        }
        ps += __shfl_xor_sync(0xffffffffu, ps, 1);
        ps += __shfl_xor_sync(0xffffffffu, ps, 2);
        if (t4 == 0) g_a2p[g_epos[e]] = ps;
    }
}

// ---------------- layer-1 softmax + aggregate + bias + elu ----------------------
__global__ void aggregate1_kernel(const float* __restrict__ bias) {
    int i = (blockIdx.x * blockDim.x + threadIdx.x) >> 5;
    int lane = threadIdx.x & 31;
    if (i >= NN) return;
    int start = g_rowptr[i], end = g_rowptr[i + 1];

    int hm = lane & 3;
    float m = -INFINITY;
    for (int j = start + (lane >> 2); j < end; j += 8)
        m = fmaxf(m, g_a1p[j * HEADS + hm]);
    m = fmaxf(m, __shfl_xor_sync(0xffffffffu, m, 4));
    m = fmaxf(m, __shfl_xor_sync(0xffffffffu, m, 8));
    m = fmaxf(m, __shfl_xor_sync(0xffffffffu, m, 16));
    int myh = lane >> 3;
    float mh = __shfl_sync(0xffffffffu, m, myh);

    float den = 0.f;
    float a0 = 0.f, a1 = 0.f, a2 = 0.f, a3 = 0.f;
    int c0 = 4 * lane;
    for (int j = start; j < end; j++) {
        float wv = __expf(g_a1p[j * HEADS + myh] - mh);
        int s = g_srcp[j];
        float4 xlv = *(const float4*)&g_xl1[s * HCD + c0];
        den += wv;
        a0 = fmaf(wv, xlv.x, a0);
        a1 = fmaf(wv, xlv.y, a1);
        a2 = fmaf(wv, xlv.z, a2);
        a3 = fmaf(wv, xlv.w, a3);
    }
    float inv = 1.f / (den + 1e-16f);
    float4 bv = *(const float4*)&bias[c0];
    float o0 = a0 * inv + bv.x;
    float o1 = a1 * inv + bv.y;
    float o2 = a2 * inv + bv.z;
    float o3 = a3 * inv + bv.w;
    o0 = o0 > 0.f ? o0 : expm1f(o0);
    o1 = o1 > 0.f ? o1 : expm1f(o1);
    o2 = o2 > 0.f ? o2 : expm1f(o2);
    o3 = o3 > 0.f ? o3 : expm1f(o3);
    *(float4*)&g_h[i * HCD + c0] = make_float4(o0, o1, o2, o3);
}

// ---------------- layer-2 softmax + aggregate + bias ----------------------------
__global__ void aggregate2_kernel(const float* __restrict__ bias, float* __restrict__ out) {
    int i = (blockIdx.x * blockDim.x + threadIdx.x) >> 5;
    int lane = threadIdx.x & 31;
    if (i >= NN) return;
    int start = g_rowptr[i], end = g_rowptr[i + 1];

    float m = -INFINITY;
    for (int j = start + lane; j < end; j += 32)
        m = fmaxf(m, g_a2p[j]);
    m = fmaxf(m, __shfl_xor_sync(0xffffffffu, m, 1));
    m = fmaxf(m, __shfl_xor_sync(0xffffffffu, m, 2));
    m = fmaxf(m, __shfl_xor_sync(0xffffffffu, m, 4));
    m = fmaxf(m, __shfl_xor_sync(0xffffffffu, m, 8));
    m = fmaxf(m, __shfl_xor_sync(0xffffffffu, m, 16));

    float den = 0.f;
    float a0 = 0.f, a1 = 0.f;
    int c0 = 2 * lane;
    for (int j = start; j < end; j++) {
        float wv = __expf(g_a2p[j] - m);
        int s = g_srcp[j];
        float2 xlv = *(const float2*)&g_xl2[s * OUTC + c0];
        den += wv;
        a0 = fmaf(wv, xlv.x, a0);
        a1 = fmaf(wv, xlv.y, a1);
    }
    float inv = 1.f / (den + 1e-16f);
    float o0 = a0 * inv + bias[c0];
    float o1 = a1 * inv + bias[c0 + 1];
    *(float2*)&out[i * OUTC + c0] = make_float2(o0, o1);
}

// ---------------- host launcher ---------------------------------------------------
extern "C" void kernel_launch(void* const* d_in, const int* in_sizes, int n_in,
                              void* d_out, int out_size) {
    const float* x    = (const float*)d_in[0];
    const int*   ei   = (const int*)  d_in[1];
    const float* ea   = (const float*)d_in[2];
    const float* Wl1  = (const float*)d_in[3];
    const float* bl1  = (const float*)d_in[4];
    const float* Wr1  = (const float*)d_in[5];
    const float* br1  = (const float*)d_in[6];
    const float* We1  = (const float*)d_in[7];
    const float* att1 = (const float*)d_in[8];
    const float* bias1= (const float*)d_in[9];
    const float* Wl2  = (const float*)d_in[10];
    const float* bl2  = (const float*)d_in[11];
    const float* Wr2  = (const float*)d_in[12];
    const float* br2  = (const float*)d_in[13];
    const float* We2  = (const float*)d_in[14];
    const float* att2 = (const float*)d_in[15];
    const float* bias2= (const float*)d_in[16];

    const int* src = ei;
    const int* dst = ei + EE;

    void *p_xl1, *p_xr1, *p_h, *p_xl2, *p_xr2, *p_deg, *p_W1p, *p_W2p;
    cudaGetSymbolAddress(&p_xl1, g_xl1);
    cudaGetSymbolAddress(&p_xr1, g_xr1);
    cudaGetSymbolAddress(&p_h,   g_h);
    cudaGetSymbolAddress(&p_xl2, g_xl2);
    cudaGetSymbolAddress(&p_xr2, g_xr2);
    cudaGetSymbolAddress(&p_deg, g_deg);
    cudaGetSymbolAddress(&p_W1p, g_W1p);
    cudaGetSymbolAddress(&p_W2p, g_W2p);

    // weight pre-pack + CSR
    prepack_kernel<<<108, 256>>>(Wl1, Wr1, Wl2, Wr2, We1, We2);
    cudaMemsetAsync(p_deg, 0, NN * sizeof(int));
    csr_count_kernel<<<(EE + 255) / 256, 256>>>(dst);
    scan_kernel<<<1, 1024>>>();
    csr_fill_kernel<<<(EE + 255) / 256, 256>>>(src, dst);

    // layer 1
    transform_direct<HCD, 256><<<dim3((NN + 127) / 128, 2), 256>>>(
        x, (const uint2*)p_W1p, bl1, br1, (float*)p_xl1, (float*)p_xr1);
    edge_logits1_direct<<<EE / 128, 256>>>(src, dst, ea, att1);
    aggregate1_kernel<<<NN / 8, 256>>>(bias1);

    // layer 2
    transform_direct<OUTC, 128><<<dim3((NN + 127) / 128, 1), 256>>>(
        (const float*)p_h, (const uint2*)p_W2p, bl2, br2, (float*)p_xl2, (float*)p_xr2);
    edge_logits2_direct<<<EE / 128, 256>>>(src, dst, ea, att2);
    aggregate2_kernel<<<NN / 8, 256>>>(bias2, (float*)d_out);
}

// round 5
// speedup vs baseline: 2.0958x; 1.0783x over previous
#include <cuda_runtime.h>
#include <math.h>

#define NN 50000
#define EE 800000
#define HCD 128
#define HEADS 4
#define OUTC 64
#define ED 32
#define NEG 0.2f

// ---------------- scratch (device globals) ------------------------------------
__device__ float g_xl1[NN * HCD];
__device__ float g_xr1[NN * HCD];
__device__ float g_h  [NN * HCD];
__device__ float g_xl2[NN * OUTC];
__device__ float g_xr2[NN * OUTC];
__device__ float g_a1p[EE * HEADS];   // logits layer1, CSR slot order, [slot][head]
__device__ float g_a2p[EE];           // logits layer2, CSR slot order
__device__ int   g_deg[NN];
__device__ int   g_rowptr[NN + 1];
__device__ int   g_cursor[NN];
__device__ int   g_eperm[EE];         // CSR slot -> edge id
__device__ int   g_srcp[EE];          // CSR slot -> src node
__device__ int   g_dstp[EE];          // CSR slot -> dst node
// pre-packed tf32 B-fragments: [kt][ntg][lane]{b0,b1}
__device__ uint2 g_W1p[16 * 32 * 32];   // K=128, TC=256
__device__ uint2 g_W2p[16 * 16 * 32];   // K=128, TC=128
__device__ uint2 g_We1p[4 * 16 * 32];   // K=32,  N=128
__device__ uint2 g_We2p[4 * 8 * 32];    // K=32,  N=64

// ---------------- helpers -------------------------------------------------------
__device__ __forceinline__ unsigned tf32_of(float f) {
    unsigned r;
    asm("cvt.rna.tf32.f32 %0, %1;" : "=r"(r) : "f"(f));
    return r;
}
__device__ __forceinline__ void mma_tf32(float* d,
                                         unsigned a0, unsigned a1, unsigned a2, unsigned a3,
                                         unsigned b0, unsigned b1) {
    asm volatile(
        "mma.sync.aligned.m16n8k8.row.col.f32.tf32.tf32.f32 "
        "{%0,%1,%2,%3}, {%4,%5,%6,%7}, {%8,%9}, {%0,%1,%2,%3};"
        : "+f"(d[0]), "+f"(d[1]), "+f"(d[2]), "+f"(d[3])
        : "r"(a0), "r"(a1), "r"(a2), "r"(a3), "r"(b0), "r"(b1));
}
__device__ __forceinline__ float lrelu(float x) { return x > 0.f ? x : NEG * x; }

// ---------------- weight fragment pre-pack --------------------------------------
__global__ void prepack_kernel(const float* __restrict__ Wl1, const float* __restrict__ Wr1,
                               const float* __restrict__ Wl2, const float* __restrict__ Wr2,
                               const float* __restrict__ We1, const float* __restrict__ We2) {
    int gw = blockIdx.x * 8 + (threadIdx.x >> 5);
    int lane = threadIdx.x & 31, g = lane >> 2, t4 = lane & 3;
    if (gw < 512) {
        int kt = gw >> 5, ntg = gw & 31;
        int c = ntg * 8 + g, k0 = kt * 8 + t4;
        float v0 = (c < 128) ? Wl1[k0 * 128 + c] : Wr1[k0 * 128 + c - 128];
        float v1 = (c < 128) ? Wl1[(k0 + 4) * 128 + c] : Wr1[(k0 + 4) * 128 + c - 128];
        g_W1p[(kt * 32 + ntg) * 32 + lane] = make_uint2(tf32_of(v0), tf32_of(v1));
    } else if (gw < 768) {
        int r = gw - 512;
        int kt = r >> 4, ntg = r & 15;
        int c = ntg * 8 + g, k0 = kt * 8 + t4;
        float v0 = (c < 64) ? Wl2[k0 * 64 + c] : Wr2[k0 * 64 + c - 64];
        float v1 = (c < 64) ? Wl2[(k0 + 4) * 64 + c] : Wr2[(k0 + 4) * 64 + c - 64];
        g_W2p[(kt * 16 + ntg) * 32 + lane] = make_uint2(tf32_of(v0), tf32_of(v1));
    } else if (gw < 832) {
        int r = gw - 768;
        int kt = r >> 4, ntg = r & 15;
        int c = ntg * 8 + g, k0 = kt * 8 + t4;
        g_We1p[(kt * 16 + ntg) * 32 + lane] =
            make_uint2(tf32_of(We1[k0 * 128 + c]), tf32_of(We1[(k0 + 4) * 128 + c]));
    } else if (gw < 864) {
        int r = gw - 832;
        int kt = r >> 3, ntg = r & 7;
        int c = ntg * 8 + g, k0 = kt * 8 + t4;
        g_We2p[(kt * 8 + ntg) * 32 + lane] =
            make_uint2(tf32_of(We2[k0 * 64 + c]), tf32_of(We2[(k0 + 4) * 64 + c]));
    }
}

// ---------------- CSR build -----------------------------------------------------
__global__ void csr_count_kernel(const int* __restrict__ dst) {
    int e = blockIdx.x * blockDim.x + threadIdx.x;
    if (e < EE) atomicAdd(&g_deg[dst[e]], 1);
}

__global__ void scan_kernel() {
    __shared__ int wtot[32];
    __shared__ int carry_sm;
    int t = threadIdx.x, lane = t & 31, wid = t >> 5;
    if (t == 0) carry_sm = 0;
    __syncthreads();
    for (int base = 0; base < NN; base += 4096) {
        int carry = carry_sm;
        int idx = base + t * 4;
        int4 v = make_int4(0, 0, 0, 0);
        if (idx + 3 < NN) v = *(const int4*)&g_deg[idx];
        else {
            if (idx     < NN) v.x = g_deg[idx];
            if (idx + 1 < NN) v.y = g_deg[idx + 1];
            if (idx + 2 < NN) v.z = g_deg[idx + 2];
        }
        int s1 = v.x + v.y, s2 = s1 + v.z, tsum = s2 + v.w;
        int sc = tsum;
        #pragma unroll
        for (int off = 1; off < 32; off <<= 1) {
            int u = __shfl_up_sync(0xffffffffu, sc, off);
            if (lane >= off) sc += u;
        }
        if (lane == 31) wtot[wid] = sc;
        __syncthreads();
        if (wid == 0) {
            int wv = wtot[lane];
            int ws = wv;
            #pragma unroll
            for (int off = 1; off < 32; off <<= 1) {
                int u = __shfl_up_sync(0xffffffffu, ws, off);
                if (lane >= off) ws += u;
            }
            wtot[lane] = ws - wv;
        }
        __syncthreads();
        int off0 = carry + wtot[wid] + (sc - tsum);
        if (idx     < NN) { g_rowptr[idx]     = off0;        g_cursor[idx]     = off0; }
        if (idx + 1 < NN) { int o = off0 + v.x; g_rowptr[idx + 1] = o; g_cursor[idx + 1] = o; }
        if (idx + 2 < NN) { int o = off0 + s1;  g_rowptr[idx + 2] = o; g_cursor[idx + 2] = o; }
        if (idx + 3 < NN) { int o = off0 + s2;  g_rowptr[idx + 3] = o; g_cursor[idx + 3] = o; }
        if (t == 1023) carry_sm = carry + wtot[31] + sc;
        __syncthreads();
    }
    if (t == 0) g_rowptr[NN] = EE;
}

__global__ void csr_fill_kernel(const int* __restrict__ src, const int* __restrict__ dst) {
    int e = blockIdx.x * blockDim.x + threadIdx.x;
    if (e < EE) {
        int d = dst[e];
        int pos = atomicAdd(&g_cursor[d], 1);
        g_eperm[pos] = e;
        g_srcp[pos] = src[e];
        g_dstp[pos] = d;
    }
}

// ---------------- node transform: direct-LDG tf32 MMA ---------------------------
template<int OUTD, int TC>
__global__ __launch_bounds__(256) void transform_direct(
    const float* __restrict__ x, const uint2* __restrict__ Wp,
    const float* __restrict__ bl, const float* __restrict__ br,
    float* __restrict__ xl, float* __restrict__ xr) {
    constexpr int NTT = TC / 8;
    int tid = threadIdx.x;
    int w = tid >> 5, lane = tid & 31, g = lane >> 2, t4 = lane & 3;
    int mrow = w & 3, ncol = w >> 2;
    int node0 = blockIdx.x * 128 + mrow * 32;
    int ntbase = blockIdx.y * 16 + ncol * 8;

    float acc[2][8][4];
    #pragma unroll
    for (int mt = 0; mt < 2; mt++)
        #pragma unroll
        for (int nt = 0; nt < 8; nt++)
            #pragma unroll
            for (int i = 0; i < 4; i++) acc[mt][nt][i] = 0.f;

    #pragma unroll 4
    for (int kt = 0; kt < 16; kt++) {
        unsigned a[2][4];
        #pragma unroll
        for (int mt = 0; mt < 2; mt++) {
            int r0 = node0 + mt * 16 + g;
            int r1 = r0 + 8;
            if (r0 >= NN) r0 = NN - 1;
            if (r1 >= NN) r1 = NN - 1;
            const float* p0 = x + r0 * 128 + kt * 8 + t4;
            const float* p1 = x + r1 * 128 + kt * 8 + t4;
            a[mt][0] = tf32_of(__ldg(p0));
            a[mt][1] = tf32_of(__ldg(p1));
            a[mt][2] = tf32_of(__ldg(p0 + 4));
            a[mt][3] = tf32_of(__ldg(p1 + 4));
        }
        const uint2* wrow = Wp + (kt * NTT + ntbase) * 32 + lane;
        #pragma unroll
        for (int nt = 0; nt < 8; nt++) {
            uint2 b = __ldg(wrow + nt * 32);
            mma_tf32(acc[0][nt], a[0][0], a[0][1], a[0][2], a[0][3], b.x, b.y);
            mma_tf32(acc[1][nt], a[1][0], a[1][1], a[1][2], a[1][3], b.x, b.y);
        }
    }

    #pragma unroll
    for (int nt = 0; nt < 8; nt++) {
        int c = (ntbase + nt) * 8 + t4 * 2;
        const float* bp; float* op; int cc;
        if (c < OUTD) { cc = c; bp = bl; op = xl; }
        else          { cc = c - OUTD; bp = br; op = xr; }
        float2 bv = *(const float2*)&bp[cc];
        #pragma unroll
        for (int mt = 0; mt < 2; mt++) {
            int n0v = node0 + mt * 16 + g;
            if (n0v < NN)
                *(float2*)&op[n0v * OUTD + cc] =
                    make_float2(acc[mt][nt][0] + bv.x, acc[mt][nt][1] + bv.y);
            int n1v = n0v + 8;
            if (n1v < NN)
                *(float2*)&op[n1v * OUTD + cc] =
                    make_float2(acc[mt][nt][2] + bv.x, acc[mt][nt][3] + bv.y);
        }
    }
}

// ---------------- layer-1 edge logits: CSR-ordered tf32 MMA ---------------------
// Warp handles 16 CSR slots: m16(edges) x n128(channels), K=32.
__global__ __launch_bounds__(256) void edge_logits1_direct(
    const float* __restrict__ ea, const float* __restrict__ att) {
    int tid = threadIdx.x;
    int w = tid >> 5, lane = tid & 31, g = lane >> 2, t4 = lane & 3;
    int sbase = blockIdx.x * 128 + w * 16;

    int e0 = g_eperm[sbase + g];
    int e1 = g_eperm[sbase + 8 + g];

    float d[16][4];
    #pragma unroll
    for (int nt = 0; nt < 16; nt++)
        #pragma unroll
        for (int i = 0; i < 4; i++) d[nt][i] = 0.f;

    #pragma unroll
    for (int kt = 0; kt < 4; kt++) {
        const float* p0 = ea + e0 * 32 + kt * 8 + t4;
        const float* p1 = ea + e1 * 32 + kt * 8 + t4;
        unsigned a0 = tf32_of(__ldg(p0));
        unsigned a1 = tf32_of(__ldg(p1));
        unsigned a2 = tf32_of(__ldg(p0 + 4));
        unsigned a3 = tf32_of(__ldg(p1 + 4));
        const uint2* wrow = g_We1p + (kt * 16) * 32 + lane;
        #pragma unroll
        for (int nt = 0; nt < 16; nt++) {
            uint2 b = __ldg(wrow + nt * 32);
            mma_tf32(d[nt], a0, a1, a2, a3, b.x, b.y);
        }
    }

    #pragma unroll
    for (int rsel = 0; rsel < 2; rsel++) {
        int slot = sbase + g + 8 * rsel;
        int s = g_srcp[slot], dd = g_dstp[slot];
        const float* xlr = g_xl1 + s * HCD;
        const float* xrr = g_xr1 + dd * HCD;
        float ph0 = 0.f, ph1 = 0.f, ph2 = 0.f, ph3 = 0.f;
        #pragma unroll
        for (int nt = 0; nt < 16; nt++) {
            int c = nt * 8 + t4 * 2;
            float2 xlv = *(const float2*)&xlr[c];
            float2 xrv = *(const float2*)&xrr[c];
            float2 atv = *(const float2*)&att[c];
            float v0 = d[nt][rsel * 2]     + xlv.x + xrv.x;
            float v1 = d[nt][rsel * 2 + 1] + xlv.y + xrv.y;
            float p = lrelu(v0) * atv.x + lrelu(v1) * atv.y;
            if      (nt < 4)  ph0 += p;
            else if (nt < 8)  ph1 += p;
            else if (nt < 12) ph2 += p;
            else              ph3 += p;
        }
        ph0 += __shfl_xor_sync(0xffffffffu, ph0, 1); ph0 += __shfl_xor_sync(0xffffffffu, ph0, 2);
        ph1 += __shfl_xor_sync(0xffffffffu, ph1, 1); ph1 += __shfl_xor_sync(0xffffffffu, ph1, 2);
        ph2 += __shfl_xor_sync(0xffffffffu, ph2, 1); ph2 += __shfl_xor_sync(0xffffffffu, ph2, 2);
        ph3 += __shfl_xor_sync(0xffffffffu, ph3, 1); ph3 += __shfl_xor_sync(0xffffffffu, ph3, 2);
        float myv = (t4 == 0) ? ph0 : (t4 == 1) ? ph1 : (t4 == 2) ? ph2 : ph3;
        g_a1p[slot * HEADS + t4] = myv;
    }
}

// ---------------- layer-2 edge logits: CSR-ordered tf32 MMA ---------------------
__global__ __launch_bounds__(256) void edge_logits2_direct(
    const float* __restrict__ ea, const float* __restrict__ att) {
    int tid = threadIdx.x;
    int w = tid >> 5, lane = tid & 31, g = lane >> 2, t4 = lane & 3;
    int sbase = blockIdx.x * 128 + w * 16;

    int e0 = g_eperm[sbase + g];
    int e1 = g_eperm[sbase + 8 + g];

    float d[8][4];
    #pragma unroll
    for (int nt = 0; nt < 8; nt++)
        #pragma unroll
        for (int i = 0; i < 4; i++) d[nt][i] = 0.f;

    #pragma unroll
    for (int kt = 0; kt < 4; kt++) {
        const float* p0 = ea + e0 * 32 + kt * 8 + t4;
        const float* p1 = ea + e1 * 32 + kt * 8 + t4;
        unsigned a0 = tf32_of(__ldg(p0));
        unsigned a1 = tf32_of(__ldg(p1));
        unsigned a2 = tf32_of(__ldg(p0 + 4));
        unsigned a3 = tf32_of(__ldg(p1 + 4));
        const uint2* wrow = g_We2p + (kt * 8) * 32 + lane;
        #pragma unroll
        for (int nt = 0; nt < 8; nt++) {
            uint2 b = __ldg(wrow + nt * 32);
            mma_tf32(d[nt], a0, a1, a2, a3, b.x, b.y);
        }
    }

    #pragma unroll
    for (int rsel = 0; rsel < 2; rsel++) {
        int slot = sbase + g + 8 * rsel;
        int s = g_srcp[slot], dd = g_dstp[slot];
        const float* xlr = g_xl2 + s * OUTC;
        const float* xrr = g_xr2 + dd * OUTC;
        float ps = 0.f;
        #pragma unroll
        for (int nt = 0; nt < 8; nt++) {
            int c = nt * 8 + t4 * 2;
            float2 xlv = *(const float2*)&xlr[c];
            float2 xrv = *(const float2*)&xrr[c];
            float2 atv = *(const float2*)&att[c];
            float v0 = d[nt][rsel * 2]     + xlv.x + xrv.x;
            float v1 = d[nt][rsel * 2 + 1] + xlv.y + xrv.y;
            ps += lrelu(v0) * atv.x + lrelu(v1) * atv.y;
        }
        ps += __shfl_xor_sync(0xffffffffu, ps, 1);
        ps += __shfl_xor_sync(0xffffffffu, ps, 2);
        if (t4 == 0) g_a2p[slot] = ps;
    }
}

// ---------------- layer-1 softmax (no max-sub) + aggregate + bias + elu ---------
__global__ void aggregate1_kernel(const float* __restrict__ bias) {
    int i = (blockIdx.x * blockDim.x + threadIdx.x) >> 5;
    int lane = threadIdx.x & 31;
    if (i >= NN) return;
    int start = g_rowptr[i], end = g_rowptr[i + 1];
    int myh = lane >> 3;

    float den = 0.f;
    float a0 = 0.f, a1 = 0.f, a2 = 0.f, a3 = 0.f;
    int c0 = 4 * lane;
    for (int j = start; j < end; j++) {
        float wv = __expf(g_a1p[j * HEADS + myh]);
        int s = g_srcp[j];
        float4 xlv = *(const float4*)&g_xl1[s * HCD + c0];
        den += wv;
        a0 = fmaf(wv, xlv.x, a0);
        a1 = fmaf(wv, xlv.y, a1);
        a2 = fmaf(wv, xlv.z, a2);
        a3 = fmaf(wv, xlv.w, a3);
    }
    float inv = 1.f / (den + 1e-16f);
    float4 bv = *(const float4*)&bias[c0];
    float o0 = a0 * inv + bv.x;
    float o1 = a1 * inv + bv.y;
    float o2 = a2 * inv + bv.z;
    float o3 = a3 * inv + bv.w;
    o0 = o0 > 0.f ? o0 : expm1f(o0);
    o1 = o1 > 0.f ? o1 : expm1f(o1);
    o2 = o2 > 0.f ? o2 : expm1f(o2);
    o3 = o3 > 0.f ? o3 : expm1f(o3);
    *(float4*)&g_h[i * HCD + c0] = make_float4(o0, o1, o2, o3);
}

// ---------------- layer-2 softmax (no max-sub) + aggregate + bias ---------------
__global__ void aggregate2_kernel(const float* __restrict__ bias, float* __restrict__ out) {
    int i = (blockIdx.x * blockDim.x + threadIdx.x) >> 5;
    int lane = threadIdx.x & 31;
    if (i >= NN) return;
    int start = g_rowptr[i], end = g_rowptr[i + 1];

    float den = 0.f;
    float a0 = 0.f, a1 = 0.f;
    int c0 = 2 * lane;
    for (int j = start; j < end; j++) {
        float wv = __expf(g_a2p[j]);
        int s = g_srcp[j];
        float2 xlv = *(const float2*)&g_xl2[s * OUTC + c0];
        den += wv;
        a0 = fmaf(wv, xlv.x, a0);
        a1 = fmaf(wv, xlv.y, a1);
    }
    float inv = 1.f / (den + 1e-16f);
    float o0 = a0 * inv + bias[c0];
    float o1 = a1 * inv + bias[c0 + 1];
    *(float2*)&out[i * OUTC + c0] = make_float2(o0, o1);
}

// ---------------- host launcher ---------------------------------------------------
extern "C" void kernel_launch(void* const* d_in, const int* in_sizes, int n_in,
                              void* d_out, int out_size) {
    const float* x    = (const float*)d_in[0];
    const int*   ei   = (const int*)  d_in[1];
    const float* ea   = (const float*)d_in[2];
    const float* Wl1  = (const float*)d_in[3];
    const float* bl1  = (const float*)d_in[4];
    const float* Wr1  = (const float*)d_in[5];
    const float* br1  = (const float*)d_in[6];
    const float* We1  = (const float*)d_in[7];
    const float* att1 = (const float*)d_in[8];
    const float* bias1= (const float*)d_in[9];
    const float* Wl2  = (const float*)d_in[10];
    const float* bl2  = (const float*)d_in[11];
    const float* Wr2  = (const float*)d_in[12];
    const float* br2  = (const float*)d_in[13];
    const float* We2  = (const float*)d_in[14];
    const float* att2 = (const float*)d_in[15];
    const float* bias2= (const float*)d_in[16];

    const int* src = ei;
    const int* dst = ei + EE;

    void *p_xl1, *p_xr1, *p_h, *p_xl2, *p_xr2, *p_deg, *p_W1p, *p_W2p;
    cudaGetSymbolAddress(&p_xl1, g_xl1);
    cudaGetSymbolAddress(&p_xr1, g_xr1);
    cudaGetSymbolAddress(&p_h,   g_h);
    cudaGetSymbolAddress(&p_xl2, g_xl2);
    cudaGetSymbolAddress(&p_xr2, g_xr2);
    cudaGetSymbolAddress(&p_deg, g_deg);
    cudaGetSymbolAddress(&p_W1p, g_W1p);
    cudaGetSymbolAddress(&p_W2p, g_W2p);

    // weight pre-pack + CSR
    prepack_kernel<<<108, 256>>>(Wl1, Wr1, Wl2, Wr2, We1, We2);
    cudaMemsetAsync(p_deg, 0, NN * sizeof(int));
    csr_count_kernel<<<(EE + 255) / 256, 256>>>(dst);
    scan_kernel<<<1, 1024>>>();
    csr_fill_kernel<<<(EE + 255) / 256, 256>>>(src, dst);

    // layer 1
    transform_direct<HCD, 256><<<dim3((NN + 127) / 128, 2), 256>>>(
        x, (const uint2*)p_W1p, bl1, br1, (float*)p_xl1, (float*)p_xr1);
    edge_logits1_direct<<<EE / 128, 256>>>(ea, att1);
    aggregate1_kernel<<<NN / 8, 256>>>(bias1);

    // layer 2
    transform_direct<OUTC, 128><<<dim3((NN + 127) / 128, 1), 256>>>(
        (const float*)p_h, (const uint2*)p_W2p, bl2, br2, (float*)p_xl2, (float*)p_xr2);
    edge_logits2_direct<<<EE / 128, 256>>>(ea, att2);
    aggregate2_kernel<<<NN / 8, 256>>>(bias2, (float*)d_out);
}